// round 10
// baseline (speedup 1.0000x reference)
#include <cuda_runtime.h>
#include <stdint.h>

#define MAX_NODES 50000
#define MAX_EDGES 1000000
#define FIN 512
#define FH  256
#define FO  64

// ---- scratch (no allocations allowed) ----
__device__ int   g_deg[MAX_NODES];
__device__ int   g_off[MAX_NODES + 1];
__device__ int   g_cur[MAX_NODES];
__device__ int   g_adj[MAX_EDGES];               // source node per CSR slot
__device__ float g_wgt[MAX_EDGES];               // dinv[row]*dinv[col] per CSR slot
__device__ float g_dinv[MAX_NODES];
__device__ float g_h1[(size_t)MAX_NODES * FH];   // x @ W1 (raw)
__device__ float g_a1[(size_t)MAX_NODES * FH];   // relu(aggregated layer-1)
__device__ float g_h2[(size_t)MAX_NODES * FO];   // a1 @ W2 (raw)

__global__ void k_zero_deg(int n) {
    int i = blockIdx.x * blockDim.x + threadIdx.x;
    if (i < n) g_deg[i] = 0;
}

__global__ void k_count(const int* __restrict__ col, int E) {
    int i = blockIdx.x * blockDim.x + threadIdx.x;
    if (i < E) atomicAdd(&g_deg[col[i]], 1);
}

// ---------------- single-block scan: offsets + cursors + dinv ----------------
__global__ void __launch_bounds__(1024) k_scan(int n, int E) {
    const int CH = (n + 1023) >> 10;
    const int tid = threadIdx.x;
    const int lane = tid & 31;
    const int wrp = tid >> 5;
    const int start = tid * CH;

    int sum = 0;
    for (int j = 0; j < CH; j++) {
        const int i = start + j;
        if (i < n) sum += g_deg[i];
    }

    __shared__ int wsum[32];
    int v = sum;
#pragma unroll
    for (int d = 1; d < 32; d <<= 1) {
        const int t = __shfl_up_sync(0xffffffffu, v, d);
        if (lane >= d) v += t;
    }
    if (lane == 31) wsum[wrp] = v;
    __syncthreads();
    if (wrp == 0) {
        int w = wsum[lane];
#pragma unroll
        for (int d = 1; d < 32; d <<= 1) {
            const int t = __shfl_up_sync(0xffffffffu, w, d);
            if (lane >= d) w += t;
        }
        wsum[lane] = w;
    }
    __syncthreads();

    int run = (v - sum) + (wrp > 0 ? wsum[wrp - 1] : 0);
    for (int j = 0; j < CH; j++) {
        const int i = start + j;
        if (i < n) {
            const int d = g_deg[i];
            g_off[i] = run;
            g_cur[i] = run;
            g_dinv[i] = rsqrtf((float)(d + 1));  // +1 self-loop
            run += d;
        }
    }
    if (tid == 1023) g_off[n] = E;
}

// ---------------- CSR fill (+ per-slot weight) ----------------
__global__ void k_fill(const int* __restrict__ row, const int* __restrict__ col, int E) {
    int e = blockIdx.x * blockDim.x + threadIdx.x;
    if (e < E) {
        const int r = row[e];
        const int c = col[e];
        const int pos = atomicAdd(&g_cur[c], 1);
        g_adj[pos] = r;
        g_wgt[pos] = g_dinv[r] * g_dinv[c];
    }
}

// ---------------- tiled fp32 GEMM: C[M,N] = A[M,K] @ B[K,N] ----------------
template<int N, int K>
__global__ void __launch_bounds__(256) k_gemm(const float* __restrict__ A,
                                              const float* __restrict__ B,
                                              float* __restrict__ C, int M) {
    constexpr int BM = 128, BN = 64, BK = 16;
    __shared__ float As[BK][BM + 1];
    __shared__ float Bs[BK][BN];

    const int tid = threadIdx.x;
    const int bm = blockIdx.x * BM;
    const int bn = blockIdx.y * BN;
    const int tx = tid & 15;
    const int ty = tid >> 4;
    const int tm0 = ty * 8;
    const int tn0 = tx * 4;

    const int ar = tid >> 2;
    const int ac = (tid & 3) * 4;
    const int br = tid >> 4;
    const int bc = (tid & 15) * 4;

    float acc[8][4];
#pragma unroll
    for (int i = 0; i < 8; i++)
#pragma unroll
        for (int j = 0; j < 4; j++) acc[i][j] = 0.f;

    for (int k0 = 0; k0 < K; k0 += BK) {
#pragma unroll
        for (int h = 0; h < 2; h++) {
            const int r = ar + h * 64;
            const int grow = bm + r;
            float4 v = make_float4(0.f, 0.f, 0.f, 0.f);
            if (grow < M)
                v = *reinterpret_cast<const float4*>(A + (size_t)grow * K + k0 + ac);
            As[ac + 0][r] = v.x; As[ac + 1][r] = v.y;
            As[ac + 2][r] = v.z; As[ac + 3][r] = v.w;
        }
        {
            const float4 bv = *reinterpret_cast<const float4*>(B + (size_t)(k0 + br) * N + bn + bc);
            *reinterpret_cast<float4*>(&Bs[br][bc]) = bv;
        }
        __syncthreads();

#pragma unroll
        for (int k = 0; k < BK; k++) {
            float ra[8], rb[4];
#pragma unroll
            for (int i = 0; i < 8; i++) ra[i] = As[k][tm0 + i];
#pragma unroll
            for (int j = 0; j < 4; j++) rb[j] = Bs[k][tn0 + j];
#pragma unroll
            for (int i = 0; i < 8; i++)
#pragma unroll
                for (int j = 0; j < 4; j++) acc[i][j] = fmaf(ra[i], rb[j], acc[i][j]);
        }
        __syncthreads();
    }

#pragma unroll
    for (int i = 0; i < 8; i++) {
        const int grow = bm + tm0 + i;
        if (grow < M) {
            float4 v = make_float4(acc[i][0], acc[i][1], acc[i][2], acc[i][3]);
            *reinterpret_cast<float4*>(C + (size_t)grow * N + bn + tn0) = v;
        }
    }
}

// ---------------- CSR gather, warp per (node, chunk) ----------------
// out[c] = b + dinv[c]^2*h[c] + sum_i w_i * h[adj_i]
template<int F, int VEC, bool RELU>
__global__ void __launch_bounds__(256) k_gather(const float* __restrict__ hs,
                                                const float* __restrict__ bias,
                                                float* __restrict__ out, int n) {
    constexpr int CHUNK = 32 * VEC;
    constexpr int CPN = F / CHUNK;
    const int wid = blockIdx.x * 8 + (threadIdx.x >> 5);
    const int node = wid / CPN;
    if (node >= n) return;
    const int chunk = wid % CPN;
    const int lane = threadIdx.x & 31;
    const int f0 = chunk * CHUNK + lane * VEC;

    const float di = g_dinv[node];
    const float di2 = di * di;

    float acc[VEC];
    if constexpr (VEC == 4) {
        const float4 v = *reinterpret_cast<const float4*>(hs + (size_t)node * F + f0);
        acc[0] = v.x * di2; acc[1] = v.y * di2; acc[2] = v.z * di2; acc[3] = v.w * di2;
    } else {
        const float2 v = *reinterpret_cast<const float2*>(hs + (size_t)node * F + f0);
        acc[0] = v.x * di2; acc[1] = v.y * di2;
    }

    const int s = g_off[node];
    const int t = g_off[node + 1];
    for (int base = s; base < t; base += 32) {
        const int idx = base + lane;
        int   a = 0;
        float w = 0.f;
        if (idx < t) { a = g_adj[idx]; w = g_wgt[idx]; }
        const int m = min(32, t - base);
        int j = 0;
        for (; j + 4 <= m; j += 4) {
            const int r0 = __shfl_sync(0xffffffffu, a, j);
            const int r1 = __shfl_sync(0xffffffffu, a, j + 1);
            const int r2 = __shfl_sync(0xffffffffu, a, j + 2);
            const int r3 = __shfl_sync(0xffffffffu, a, j + 3);
            const float w0 = __shfl_sync(0xffffffffu, w, j);
            const float w1 = __shfl_sync(0xffffffffu, w, j + 1);
            const float w2 = __shfl_sync(0xffffffffu, w, j + 2);
            const float w3 = __shfl_sync(0xffffffffu, w, j + 3);
            if constexpr (VEC == 4) {
                const float4 v0 = __ldg(reinterpret_cast<const float4*>(hs + (size_t)r0 * F + f0));
                const float4 v1 = __ldg(reinterpret_cast<const float4*>(hs + (size_t)r1 * F + f0));
                const float4 v2 = __ldg(reinterpret_cast<const float4*>(hs + (size_t)r2 * F + f0));
                const float4 v3 = __ldg(reinterpret_cast<const float4*>(hs + (size_t)r3 * F + f0));
                acc[0] += fmaf(w0, v0.x, fmaf(w1, v1.x, fmaf(w2, v2.x, w3 * v3.x)));
                acc[1] += fmaf(w0, v0.y, fmaf(w1, v1.y, fmaf(w2, v2.y, w3 * v3.y)));
                acc[2] += fmaf(w0, v0.z, fmaf(w1, v1.z, fmaf(w2, v2.z, w3 * v3.z)));
                acc[3] += fmaf(w0, v0.w, fmaf(w1, v1.w, fmaf(w2, v2.w, w3 * v3.w)));
            } else {
                const float2 v0 = __ldg(reinterpret_cast<const float2*>(hs + (size_t)r0 * F + f0));
                const float2 v1 = __ldg(reinterpret_cast<const float2*>(hs + (size_t)r1 * F + f0));
                const float2 v2 = __ldg(reinterpret_cast<const float2*>(hs + (size_t)r2 * F + f0));
                const float2 v3 = __ldg(reinterpret_cast<const float2*>(hs + (size_t)r3 * F + f0));
                acc[0] += fmaf(w0, v0.x, fmaf(w1, v1.x, fmaf(w2, v2.x, w3 * v3.x)));
                acc[1] += fmaf(w0, v0.y, fmaf(w1, v1.y, fmaf(w2, v2.y, w3 * v3.y)));
            }
        }
        for (; j < m; j++) {
            const int rr = __shfl_sync(0xffffffffu, a, j);
            const float ww = __shfl_sync(0xffffffffu, w, j);
            if constexpr (VEC == 4) {
                const float4 v = __ldg(reinterpret_cast<const float4*>(hs + (size_t)rr * F + f0));
                acc[0] = fmaf(ww, v.x, acc[0]); acc[1] = fmaf(ww, v.y, acc[1]);
                acc[2] = fmaf(ww, v.z, acc[2]); acc[3] = fmaf(ww, v.w, acc[3]);
            } else {
                const float2 v = __ldg(reinterpret_cast<const float2*>(hs + (size_t)rr * F + f0));
                acc[0] = fmaf(ww, v.x, acc[0]); acc[1] = fmaf(ww, v.y, acc[1]);
            }
        }
    }

    if constexpr (VEC == 4) {
        const float4 b = *reinterpret_cast<const float4*>(bias + f0);
        float4 o = make_float4(acc[0] + b.x, acc[1] + b.y, acc[2] + b.z, acc[3] + b.w);
        if (RELU) {
            o.x = fmaxf(o.x, 0.f); o.y = fmaxf(o.y, 0.f);
            o.z = fmaxf(o.z, 0.f); o.w = fmaxf(o.w, 0.f);
        }
        *reinterpret_cast<float4*>(out + (size_t)node * F + f0) = o;
    } else {
        const float2 b = *reinterpret_cast<const float2*>(bias + f0);
        float2 o = make_float2(acc[0] + b.x, acc[1] + b.y);
        if (RELU) { o.x = fmaxf(o.x, 0.f); o.y = fmaxf(o.y, 0.f); }
        *reinterpret_cast<float2*>(out + (size_t)node * F + f0) = o;
    }
}

extern "C" void kernel_launch(void* const* d_in, const int* in_sizes, int n_in,
                              void* d_out, int out_size) {
    const float* x   = (const float*)d_in[0];
    const int*   ei  = (const int*)d_in[1];
    const float* W1  = (const float*)d_in[2];
    const float* b1  = (const float*)d_in[3];
    const float* W2  = (const float*)d_in[4];
    const float* b2  = (const float*)d_in[5];
    float*       out = (float*)d_out;

    const int M = in_sizes[0] / FIN;        // 50000
    const int E = in_sizes[1] / 2;          // 800000
    const int* row = ei;
    const int* col = ei + E;

    const int T = 256;
    const int nblk = (M + 255) / 256;

    k_zero_deg<<<nblk, T>>>(M);                                   // 0
    k_count<<<(E + T - 1) / T, T>>>(col, E);                      // 1
    k_scan<<<1, 1024>>>(M, E);                                    // 2
    k_fill<<<(E + T - 1) / T, T>>>(row, col, E);                  // 3 <- profiled slot
    {                                                             // 4: gemm1
        dim3 grid((M + 127) / 128, FH / 64);
        k_gemm<FH, FIN><<<grid, T>>>(x, W1, g_h1, M);
    }
    {   // 5 + 6: gather1 LAUNCHED TWICE (idempotent) — dur delta vs R6 measures its true cost
        const int warps = M * (FH / 128);
        k_gather<FH, 4, true><<<(warps + 7) / 8, T>>>(g_h1, b1, g_a1, M);
        k_gather<FH, 4, true><<<(warps + 7) / 8, T>>>(g_h1, b1, g_a1, M);
    }
    {                                                             // 7: gemm2
        dim3 grid((M + 127) / 128, FO / 64);
        k_gemm<FO, FH><<<grid, T>>>(g_a1, W2, g_h2, M);
    }
    {   // 8 + 9: gather2 LAUNCHED TWICE (idempotent)
        const int warps = M;
        k_gather<FO, 2, false><<<(warps + 7) / 8, T>>>(g_h2, b2, out, M);
        k_gather<FO, 2, false><<<(warps + 7) / 8, T>>>(g_h2, b2, out, M);
    }
}

// round 11
// speedup vs baseline: 1.8686x; 1.8686x over previous
#include <cuda_runtime.h>
#include <stdint.h>

#define MAX_NODES 50000
#define MAX_EDGES 1000000
#define FIN 512
#define FH  256
#define FO  64

// ---- scratch (no allocations allowed) ----
__device__ int   g_deg[MAX_NODES];
__device__ int   g_off[MAX_NODES + 1];
__device__ int   g_cur[MAX_NODES];
__device__ int   g_adj[MAX_EDGES];               // source node per CSR slot
__device__ float g_wgt[MAX_EDGES];               // dinv[row]*dinv[col] per CSR slot
__device__ float g_dinv[MAX_NODES];
__device__ float g_h1[(size_t)MAX_NODES * FH];   // x @ W1 (raw)
__device__ float g_a1[(size_t)MAX_NODES * FH];   // relu(aggregated layer-1)
__device__ float g_h2[(size_t)MAX_NODES * FO];   // a1 @ W2 (raw)

__global__ void k_zero_deg(int n) {
    int i = blockIdx.x * blockDim.x + threadIdx.x;
    if (i < n) g_deg[i] = 0;
}

__global__ void k_count(const int* __restrict__ col, int E) {
    int i = blockIdx.x * blockDim.x + threadIdx.x;
    if (i < E) atomicAdd(&g_deg[col[i]], 1);
}

// ---------------- single-block scan: offsets + cursors + dinv ----------------
__global__ void __launch_bounds__(1024) k_scan(int n, int E) {
    const int CH = (n + 1023) >> 10;
    const int tid = threadIdx.x;
    const int lane = tid & 31;
    const int wrp = tid >> 5;
    const int start = tid * CH;

    int sum = 0;
    for (int j = 0; j < CH; j++) {
        const int i = start + j;
        if (i < n) sum += g_deg[i];
    }

    __shared__ int wsum[32];
    int v = sum;
#pragma unroll
    for (int d = 1; d < 32; d <<= 1) {
        const int t = __shfl_up_sync(0xffffffffu, v, d);
        if (lane >= d) v += t;
    }
    if (lane == 31) wsum[wrp] = v;
    __syncthreads();
    if (wrp == 0) {
        int w = wsum[lane];
#pragma unroll
        for (int d = 1; d < 32; d <<= 1) {
            const int t = __shfl_up_sync(0xffffffffu, w, d);
            if (lane >= d) w += t;
        }
        wsum[lane] = w;
    }
    __syncthreads();

    int run = (v - sum) + (wrp > 0 ? wsum[wrp - 1] : 0);
    for (int j = 0; j < CH; j++) {
        const int i = start + j;
        if (i < n) {
            const int d = g_deg[i];
            g_off[i] = run;
            g_cur[i] = run;
            g_dinv[i] = rsqrtf((float)(d + 1));  // +1 self-loop
            run += d;
        }
    }
    if (tid == 1023) g_off[n] = E;
}

// ---------------- CSR fill (+ per-slot weight) ----------------
__global__ void k_fill(const int* __restrict__ row, const int* __restrict__ col, int E) {
    int e = blockIdx.x * blockDim.x + threadIdx.x;
    if (e < E) {
        const int r = row[e];
        const int c = col[e];
        const int pos = atomicAdd(&g_cur[c], 1);
        g_adj[pos] = r;
        g_wgt[pos] = g_dinv[r] * g_dinv[c];
    }
}

// ---------------- tiled fp32 GEMM: C[M,N] = A[M,K] @ B[K,N] ----------------
template<int N, int K>
__global__ void __launch_bounds__(256) k_gemm(const float* __restrict__ A,
                                              const float* __restrict__ B,
                                              float* __restrict__ C, int M) {
    constexpr int BM = 128, BN = 64, BK = 16;
    __shared__ float As[BK][BM + 1];
    __shared__ float Bs[BK][BN];

    const int tid = threadIdx.x;
    const int bm = blockIdx.x * BM;
    const int bn = blockIdx.y * BN;
    const int tx = tid & 15;
    const int ty = tid >> 4;
    const int tm0 = ty * 8;
    const int tn0 = tx * 4;

    const int ar = tid >> 2;
    const int ac = (tid & 3) * 4;
    const int br = tid >> 4;
    const int bc = (tid & 15) * 4;

    float acc[8][4];
#pragma unroll
    for (int i = 0; i < 8; i++)
#pragma unroll
        for (int j = 0; j < 4; j++) acc[i][j] = 0.f;

    for (int k0 = 0; k0 < K; k0 += BK) {
#pragma unroll
        for (int h = 0; h < 2; h++) {
            const int r = ar + h * 64;
            const int grow = bm + r;
            float4 v = make_float4(0.f, 0.f, 0.f, 0.f);
            if (grow < M)
                v = *reinterpret_cast<const float4*>(A + (size_t)grow * K + k0 + ac);
            As[ac + 0][r] = v.x; As[ac + 1][r] = v.y;
            As[ac + 2][r] = v.z; As[ac + 3][r] = v.w;
        }
        {
            const float4 bv = *reinterpret_cast<const float4*>(B + (size_t)(k0 + br) * N + bn + bc);
            *reinterpret_cast<float4*>(&Bs[br][bc]) = bv;
        }
        __syncthreads();

#pragma unroll
        for (int k = 0; k < BK; k++) {
            float ra[8], rb[4];
#pragma unroll
            for (int i = 0; i < 8; i++) ra[i] = As[k][tm0 + i];
#pragma unroll
            for (int j = 0; j < 4; j++) rb[j] = Bs[k][tn0 + j];
#pragma unroll
            for (int i = 0; i < 8; i++)
#pragma unroll
                for (int j = 0; j < 4; j++) acc[i][j] = fmaf(ra[i], rb[j], acc[i][j]);
        }
        __syncthreads();
    }

#pragma unroll
    for (int i = 0; i < 8; i++) {
        const int grow = bm + tm0 + i;
        if (grow < M) {
            float4 v = make_float4(acc[i][0], acc[i][1], acc[i][2], acc[i][3]);
            *reinterpret_cast<float4*>(C + (size_t)grow * N + bn + tn0) = v;
        }
    }
}

// ---------------- CSR gather v3: thread per (node, float4 chunk) ----------------
// Plain loads (no __ldg / .CONSTANT path), 4x-unrolled INDEPENDENT loads per lane
// (128 loads in flight per warp). adj/wgt reads broadcast within node group.
// out[c] = b + dinv[c]^2*h[c] + sum_i w_i * h[adj_i]
template<int F, bool RELU>
__global__ void __launch_bounds__(256) k_gather3(const float* __restrict__ hs,
                                                 const float* __restrict__ bias,
                                                 float* __restrict__ out, int n) {
    constexpr int TPN = F / 4;                 // threads per node
    const int gid = blockIdx.x * 256 + threadIdx.x;
    const int node = gid / TPN;
    if (node >= n) return;
    const int f0 = (gid % TPN) * 4;

    const float di = g_dinv[node];
    const float di2 = di * di;

    const float4 sv = *reinterpret_cast<const float4*>(hs + (size_t)node * F + f0);
    float ax = sv.x * di2, ay = sv.y * di2, az = sv.z * di2, aw = sv.w * di2;

    const int s = g_off[node];
    const int t = g_off[node + 1];
    int i = s;
    for (; i + 4 <= t; i += 4) {
        const int   r0 = g_adj[i],     r1 = g_adj[i + 1],
                    r2 = g_adj[i + 2], r3 = g_adj[i + 3];
        const float w0 = g_wgt[i],     w1 = g_wgt[i + 1],
                    w2 = g_wgt[i + 2], w3 = g_wgt[i + 3];
        const float4 v0 = *reinterpret_cast<const float4*>(hs + (size_t)r0 * F + f0);
        const float4 v1 = *reinterpret_cast<const float4*>(hs + (size_t)r1 * F + f0);
        const float4 v2 = *reinterpret_cast<const float4*>(hs + (size_t)r2 * F + f0);
        const float4 v3 = *reinterpret_cast<const float4*>(hs + (size_t)r3 * F + f0);
        ax += fmaf(w0, v0.x, fmaf(w1, v1.x, fmaf(w2, v2.x, w3 * v3.x)));
        ay += fmaf(w0, v0.y, fmaf(w1, v1.y, fmaf(w2, v2.y, w3 * v3.y)));
        az += fmaf(w0, v0.z, fmaf(w1, v1.z, fmaf(w2, v2.z, w3 * v3.z)));
        aw += fmaf(w0, v0.w, fmaf(w1, v1.w, fmaf(w2, v2.w, w3 * v3.w)));
    }
    for (; i < t; i++) {
        const int   r = g_adj[i];
        const float w = g_wgt[i];
        const float4 v = *reinterpret_cast<const float4*>(hs + (size_t)r * F + f0);
        ax = fmaf(w, v.x, ax); ay = fmaf(w, v.y, ay);
        az = fmaf(w, v.z, az); aw = fmaf(w, v.w, aw);
    }

    const float4 b = *reinterpret_cast<const float4*>(bias + f0);
    float4 o = make_float4(ax + b.x, ay + b.y, az + b.z, aw + b.w);
    if (RELU) {
        o.x = fmaxf(o.x, 0.f); o.y = fmaxf(o.y, 0.f);
        o.z = fmaxf(o.z, 0.f); o.w = fmaxf(o.w, 0.f);
    }
    *reinterpret_cast<float4*>(out + (size_t)node * F + f0) = o;
}

extern "C" void kernel_launch(void* const* d_in, const int* in_sizes, int n_in,
                              void* d_out, int out_size) {
    const float* x   = (const float*)d_in[0];
    const int*   ei  = (const int*)d_in[1];
    const float* W1  = (const float*)d_in[2];
    const float* b1  = (const float*)d_in[3];
    const float* W2  = (const float*)d_in[4];
    const float* b2  = (const float*)d_in[5];
    float*       out = (float*)d_out;

    const int M = in_sizes[0] / FIN;        // 50000
    const int E = in_sizes[1] / 2;          // 800000
    const int* row = ei;
    const int* col = ei + E;

    const int T = 256;
    const int nblk = (M + 255) / 256;

    k_zero_deg<<<nblk, T>>>(M);                                   // 0
    k_count<<<(E + T - 1) / T, T>>>(col, E);                      // 1
    k_scan<<<1, 1024>>>(M, E);                                    // 2
    k_fill<<<(E + T - 1) / T, T>>>(row, col, E);                  // 3 <- profiled slot
    {                                                             // 4: gemm1
        dim3 grid((M + 127) / 128, FH / 64);
        k_gemm<FH, FIN><<<grid, T>>>(x, W1, g_h1, M);
    }
    {                                                             // 5: gather1 (relu)
        const int threads = M * (FH / 4);
        k_gather3<FH, true><<<(threads + T - 1) / T, T>>>(g_h1, b1, g_a1, M);
    }
    {                                                             // 6: gemm2
        dim3 grid((M + 127) / 128, FO / 64);
        k_gemm<FO, FH><<<grid, T>>>(g_a1, W2, g_h2, M);
    }
    {                                                             // 7: gather2
        const int threads = M * (FO / 4);
        k_gather3<FO, false><<<(threads + T - 1) / T, T>>>(g_h2, b2, out, M);
    }
}

// round 12
// speedup vs baseline: 1.8721x; 1.0019x over previous
#include <cuda_runtime.h>
#include <stdint.h>

#define MAX_NODES 50000
#define MAX_EDGES 1000000
#define FIN 512
#define FH  256
#define FO  64

// ---- scratch (no allocations allowed) ----
__device__ int   g_deg[MAX_NODES];
__device__ int   g_off[MAX_NODES + 1];
__device__ int   g_cur[MAX_NODES];
__device__ int   g_adj[MAX_EDGES];               // source node per CSR slot
__device__ float g_wgt[MAX_EDGES];               // dinv[row]*dinv[col] per CSR slot
__device__ float g_dinv[MAX_NODES];
__device__ float g_h1[(size_t)MAX_NODES * FH];   // x @ W1 (raw)
__device__ float g_a1[(size_t)MAX_NODES * FH];   // relu(aggregated layer-1)
__device__ float g_h2[(size_t)MAX_NODES * FO];   // a1 @ W2 (raw)

__global__ void k_zero_deg(int n) {
    int i = blockIdx.x * blockDim.x + threadIdx.x;
    if (i < n) g_deg[i] = 0;
}

__global__ void k_count(const int* __restrict__ col, int E) {
    int i = blockIdx.x * blockDim.x + threadIdx.x;
    if (i < E) atomicAdd(&g_deg[col[i]], 1);
}

// ---------------- single-block scan: offsets + cursors + dinv ----------------
__global__ void __launch_bounds__(1024) k_scan(int n, int E) {
    const int CH = (n + 1023) >> 10;
    const int tid = threadIdx.x;
    const int lane = tid & 31;
    const int wrp = tid >> 5;
    const int start = tid * CH;

    int sum = 0;
    for (int j = 0; j < CH; j++) {
        const int i = start + j;
        if (i < n) sum += g_deg[i];
    }

    __shared__ int wsum[32];
    int v = sum;
#pragma unroll
    for (int d = 1; d < 32; d <<= 1) {
        const int t = __shfl_up_sync(0xffffffffu, v, d);
        if (lane >= d) v += t;
    }
    if (lane == 31) wsum[wrp] = v;
    __syncthreads();
    if (wrp == 0) {
        int w = wsum[lane];
#pragma unroll
        for (int d = 1; d < 32; d <<= 1) {
            const int t = __shfl_up_sync(0xffffffffu, w, d);
            if (lane >= d) w += t;
        }
        wsum[lane] = w;
    }
    __syncthreads();

    int run = (v - sum) + (wrp > 0 ? wsum[wrp - 1] : 0);
    for (int j = 0; j < CH; j++) {
        const int i = start + j;
        if (i < n) {
            const int d = g_deg[i];
            g_off[i] = run;
            g_cur[i] = run;
            g_dinv[i] = rsqrtf((float)(d + 1));  // +1 self-loop
            run += d;
        }
    }
    if (tid == 1023) g_off[n] = E;
}

// ---------------- CSR fill (+ per-slot weight) ----------------
__global__ void k_fill(const int* __restrict__ row, const int* __restrict__ col, int E) {
    int e = blockIdx.x * blockDim.x + threadIdx.x;
    if (e < E) {
        const int r = row[e];
        const int c = col[e];
        const int pos = atomicAdd(&g_cur[c], 1);
        g_adj[pos] = r;
        g_wgt[pos] = g_dinv[r] * g_dinv[c];
    }
}

// ---------------- tiled fp32 GEMM: C[M,N] = A[M,K] @ B[K,N] ----------------
template<int N, int K>
__global__ void __launch_bounds__(256) k_gemm(const float* __restrict__ A,
                                              const float* __restrict__ B,
                                              float* __restrict__ C, int M) {
    constexpr int BM = 128, BN = 64, BK = 16;
    __shared__ float As[BK][BM + 1];
    __shared__ float Bs[BK][BN];

    const int tid = threadIdx.x;
    const int bm = blockIdx.x * BM;
    const int bn = blockIdx.y * BN;
    const int tx = tid & 15;
    const int ty = tid >> 4;
    const int tm0 = ty * 8;
    const int tn0 = tx * 4;

    const int ar = tid >> 2;
    const int ac = (tid & 3) * 4;
    const int br = tid >> 4;
    const int bc = (tid & 15) * 4;

    float acc[8][4];
#pragma unroll
    for (int i = 0; i < 8; i++)
#pragma unroll
        for (int j = 0; j < 4; j++) acc[i][j] = 0.f;

    for (int k0 = 0; k0 < K; k0 += BK) {
#pragma unroll
        for (int h = 0; h < 2; h++) {
            const int r = ar + h * 64;
            const int grow = bm + r;
            float4 v = make_float4(0.f, 0.f, 0.f, 0.f);
            if (grow < M)
                v = *reinterpret_cast<const float4*>(A + (size_t)grow * K + k0 + ac);
            As[ac + 0][r] = v.x; As[ac + 1][r] = v.y;
            As[ac + 2][r] = v.z; As[ac + 3][r] = v.w;
        }
        {
            const float4 bv = *reinterpret_cast<const float4*>(B + (size_t)(k0 + br) * N + bn + bc);
            *reinterpret_cast<float4*>(&Bs[br][bc]) = bv;
        }
        __syncthreads();

#pragma unroll
        for (int k = 0; k < BK; k++) {
            float ra[8], rb[4];
#pragma unroll
            for (int i = 0; i < 8; i++) ra[i] = As[k][tm0 + i];
#pragma unroll
            for (int j = 0; j < 4; j++) rb[j] = Bs[k][tn0 + j];
#pragma unroll
            for (int i = 0; i < 8; i++)
#pragma unroll
                for (int j = 0; j < 4; j++) acc[i][j] = fmaf(ra[i], rb[j], acc[i][j]);
        }
        __syncthreads();
    }

#pragma unroll
    for (int i = 0; i < 8; i++) {
        const int grow = bm + tm0 + i;
        if (grow < M) {
            float4 v = make_float4(acc[i][0], acc[i][1], acc[i][2], acc[i][3]);
            *reinterpret_cast<float4*>(C + (size_t)grow * N + bn + tn0) = v;
        }
    }
}

// ---------------- CSR gather v3: thread per (node, float4 chunk) ----------------
// Plain loads (no __ldg / .CONSTANT path), 4x-unrolled INDEPENDENT loads per lane
// (128 loads in flight per warp). adj/wgt reads broadcast within node group.
// out[c] = b + dinv[c]^2*h[c] + sum_i w_i * h[adj_i]
template<int F, bool RELU>
__global__ void __launch_bounds__(256) k_gather3(const float* __restrict__ hs,
                                                 const float* __restrict__ bias,
                                                 float* __restrict__ out, int n) {
    constexpr int TPN = F / 4;                 // threads per node
    const int gid = blockIdx.x * 256 + threadIdx.x;
    const int node = gid / TPN;
    if (node >= n) return;
    const int f0 = (gid % TPN) * 4;

    const float di = g_dinv[node];
    const float di2 = di * di;

    const float4 sv = *reinterpret_cast<const float4*>(hs + (size_t)node * F + f0);
    float ax = sv.x * di2, ay = sv.y * di2, az = sv.z * di2, aw = sv.w * di2;

    const int s = g_off[node];
    const int t = g_off[node + 1];
    int i = s;
    for (; i + 4 <= t; i += 4) {
        const int   r0 = g_adj[i],     r1 = g_adj[i + 1],
                    r2 = g_adj[i + 2], r3 = g_adj[i + 3];
        const float w0 = g_wgt[i],     w1 = g_wgt[i + 1],
                    w2 = g_wgt[i + 2], w3 = g_wgt[i + 3];
        const float4 v0 = *reinterpret_cast<const float4*>(hs + (size_t)r0 * F + f0);
        const float4 v1 = *reinterpret_cast<const float4*>(hs + (size_t)r1 * F + f0);
        const float4 v2 = *reinterpret_cast<const float4*>(hs + (size_t)r2 * F + f0);
        const float4 v3 = *reinterpret_cast<const float4*>(hs + (size_t)r3 * F + f0);
        ax += fmaf(w0, v0.x, fmaf(w1, v1.x, fmaf(w2, v2.x, w3 * v3.x)));
        ay += fmaf(w0, v0.y, fmaf(w1, v1.y, fmaf(w2, v2.y, w3 * v3.y)));
        az += fmaf(w0, v0.z, fmaf(w1, v1.z, fmaf(w2, v2.z, w3 * v3.z)));
        aw += fmaf(w0, v0.w, fmaf(w1, v1.w, fmaf(w2, v2.w, w3 * v3.w)));
    }
    for (; i < t; i++) {
        const int   r = g_adj[i];
        const float w = g_wgt[i];
        const float4 v = *reinterpret_cast<const float4*>(hs + (size_t)r * F + f0);
        ax = fmaf(w, v.x, ax); ay = fmaf(w, v.y, ay);
        az = fmaf(w, v.z, az); aw = fmaf(w, v.w, aw);
    }

    const float4 b = *reinterpret_cast<const float4*>(bias + f0);
    float4 o = make_float4(ax + b.x, ay + b.y, az + b.z, aw + b.w);
    if (RELU) {
        o.x = fmaxf(o.x, 0.f); o.y = fmaxf(o.y, 0.f);
        o.z = fmaxf(o.z, 0.f); o.w = fmaxf(o.w, 0.f);
    }
    *reinterpret_cast<float4*>(out + (size_t)node * F + f0) = o;
}

extern "C" void kernel_launch(void* const* d_in, const int* in_sizes, int n_in,
                              void* d_out, int out_size) {
    const float* x   = (const float*)d_in[0];
    const int*   ei  = (const int*)d_in[1];
    const float* W1  = (const float*)d_in[2];
    const float* b1  = (const float*)d_in[3];
    const float* W2  = (const float*)d_in[4];
    const float* b2  = (const float*)d_in[5];
    float*       out = (float*)d_out;

    const int M = in_sizes[0] / FIN;        // 50000
    const int E = in_sizes[1] / 2;          // 800000
    const int* row = ei;
    const int* col = ei + E;

    const int T = 256;
    const int nblk = (M + 255) / 256;

    k_zero_deg<<<nblk, T>>>(M);                                   // 0
    k_count<<<(E + T - 1) / T, T>>>(col, E);                      // 1
    k_scan<<<1, 1024>>>(M, E);                                    // 2
    k_fill<<<(E + T - 1) / T, T>>>(row, col, E);                  // 3 <- profiled slot
    {                                                             // 4: gemm1
        dim3 grid((M + 127) / 128, FH / 64);
        k_gemm<FH, FIN><<<grid, T>>>(x, W1, g_h1, M);
    }
    {                                                             // 5: gather1 (relu)
        const int threads = M * (FH / 4);
        k_gather3<FH, true><<<(threads + T - 1) / T, T>>>(g_h1, b1, g_a1, M);
    }
    {                                                             // 6: gemm2
        dim3 grid((M + 127) / 128, FO / 64);
        k_gemm<FO, FH><<<grid, T>>>(g_a1, W2, g_h2, M);
    }
    {                                                             // 7: gather2
        const int threads = M * (FO / 4);
        k_gather3<FO, false><<<(threads + T - 1) / T, T>>>(g_h2, b2, out, M);
    }
}